// round 16
// baseline (speedup 1.0000x reference)
#include <cuda_runtime.h>
#include <mma.h>
#include <cuda_fp16.h>
#include <cuda_pipeline.h>

using namespace nvcuda;

#define EMB   1024
#define NH    16
#define HS    64
#define BATCH 4
#define SEQ   2048
#define MROWS (BATCH * SEQ)   // 8192
#define N3    (3 * EMB)       // 3072

// Scratch (allocation-free rule: __device__ globals)
__device__ __half x_h[MROWS * EMB];
__device__ __half wqkv_h[EMB * N3];
__device__ __half wout_h[EMB * EMB];
__device__ __half qkv_h[MROWS * N3];     // q pre-scaled+biased; k,v biased
__device__ __half g_att_h[MROWS * EMB];  // [B][T][C] head-concat

__device__ __forceinline__ void st_half4(__half* p, float4 v) {
    *(__half2*)(p)     = __floats2half2_rn(v.x, v.y);
    *(__half2*)(p + 2) = __floats2half2_rn(v.z, v.w);
}

// ---------------------------------------------------------------------------
// float -> half conversion
// ---------------------------------------------------------------------------
__global__ __launch_bounds__(256) void f2h_kernel(
    const float* __restrict__ src, __half* __restrict__ dst)
{
    const int i = (blockIdx.x * 256 + threadIdx.x) * 8;
    const float4 a = *(const float4*)(src + i);
    const float4 b = *(const float4*)(src + i + 4);
    st_half4(dst + i, a);
    st_half4(dst + i + 4, b);
}

// ---------------------------------------------------------------------------
// FP16 WMMA GEMM, cp.async 3-stage pipeline.
//   C[8192, N] = A_h[8192, 1024] @ W_h[1024, N] + bias  (optional q-scale)
// block 128x256, BK=16, 256 threads = 8 warps (2 m x 4 n), warp tile 64x64:
// per k-tile 4 af + 4 bf fragment loads feed 16 mma (ratio 2.0).
// ---------------------------------------------------------------------------
#define ALDH 24                 // halfs per A row (16 + 8)
#define BLDH 264                // halfs per B k-row (256 + 8)
#define ABUFH (128 * ALDH)      // 3072 halfs
#define BBUFH (16 * BLDH)       // 4224 halfs
#define STAGEH (ABUFH + BBUFH)  // 7296 halfs = 14592 B
#define GEMM_SMEM_BYTES (3 * STAGEH * 2)   // 43776 B (> epilogue 34816)

__global__ __launch_bounds__(256) void gemm_h_kernel(
    const __half* __restrict__ A, const __half* __restrict__ W,
    const float* __restrict__ bias,
    __half* __restrict__ Ch, float* __restrict__ Cf,
    int N, int qscale_flag)
{
    extern __shared__ char smraw[];
    __half* smh = (__half*)smraw;

    const int tid  = threadIdx.x;
    const int lane = tid & 31, warp = tid >> 5;
    const int bm = blockIdx.y, bn = blockIdx.x;
    const int wm = (warp & 1) * 64;      // 2 warps in m
    const int wn = (warp >> 1) * 64;     // 4 warps in n

    // hoisted cp.async addressing (per-thread constants)
    const int arow = tid >> 1, ac = (tid & 1) * 8;
    const int brow = tid >> 4, bc8 = (tid & 15) * 8;   // + second chunk +128
    const __half* aSrc = A + (size_t)(bm * 128 + arow) * EMB + ac;
    const __half* bSrc = W + (size_t)brow * N + bn * 256 + bc8;
    const int aOff = arow * ALDH + ac;
    const int bOff = ABUFH + brow * BLDH + bc8;

#define GEMM_ISSUE(stage, kt)                                               \
    do {                                                                    \
        __pipeline_memcpy_async(&smh[(stage) * STAGEH + aOff],              \
                                aSrc + (kt) * 16, 16);                      \
        __pipeline_memcpy_async(&smh[(stage) * STAGEH + bOff],              \
                                bSrc + (size_t)(kt) * 16 * N, 16);          \
        __pipeline_memcpy_async(&smh[(stage) * STAGEH + bOff + 128],        \
                                bSrc + (size_t)(kt) * 16 * N + 128, 16);    \
        __pipeline_commit();                                                \
    } while (0)

    wmma::fragment<wmma::accumulator, 16, 16, 16, float> acc[4][4];
#pragma unroll
    for (int mt = 0; mt < 4; mt++)
#pragma unroll
        for (int nt = 0; nt < 4; nt++)
            wmma::fill_fragment(acc[mt][nt], 0.0f);

    // prologue: tiles 0,1 -> stages 0,1
    GEMM_ISSUE(0, 0);
    GEMM_ISSUE(1, 1);

    const int NK = EMB / 16;   // 64
    for (int kt = 0; kt < NK; kt++) {
        const int rem = NK - kt;
        if (rem >= 2)      __pipeline_wait_prior(1);
        else               __pipeline_wait_prior(0);
        __syncthreads();

        const __half* As = smh + (kt % 3) * STAGEH;
        const __half* Bs = As + ABUFH;
        {
            wmma::fragment<wmma::matrix_a, 16, 16, 16, __half,
                           wmma::row_major> af[4];
            wmma::fragment<wmma::matrix_b, 16, 16, 16, __half,
                           wmma::row_major> bf[4];
#pragma unroll
            for (int mt = 0; mt < 4; mt++)
                wmma::load_matrix_sync(af[mt],
                    &As[(wm + mt * 16) * ALDH], ALDH);
#pragma unroll
            for (int nt = 0; nt < 4; nt++)
                wmma::load_matrix_sync(bf[nt], &Bs[wn + nt * 16], BLDH);
#pragma unroll
            for (int mt = 0; mt < 4; mt++)
#pragma unroll
                for (int nt = 0; nt < 4; nt++)
                    wmma::mma_sync(acc[mt][nt], af[mt], bf[nt], acc[mt][nt]);
        }

        if (kt + 2 < NK)
            GEMM_ISSUE((kt + 2) % 3, kt + 2);
    }
#undef GEMM_ISSUE

    // ---- epilogue: stage via smem, fuse bias (+q-scale), write ----
    __syncthreads();           // all warps done reading pipeline buffers
    float* stg = (float*)smraw + warp * (16 * 68);
    const int r  = lane >> 1;
    const int c0 = (lane & 1) * 32;
#pragma unroll
    for (int mt = 0; mt < 4; mt++) {
#pragma unroll
        for (int nt = 0; nt < 4; nt++)
            wmma::store_matrix_sync(&stg[nt * 16], acc[mt][nt], 68,
                                    wmma::mem_row_major);
        __syncwarp();
        const int grow = bm * 128 + wm + mt * 16 + r;
        const int gcol = bn * 256 + wn + c0;   // multiple of 32
        const float qs = (qscale_flag && gcol < EMB) ? 0.125f : 1.0f;
#pragma unroll
        for (int j = 0; j < 32; j += 4) {
            float4 v = *(const float4*)&stg[r * 68 + c0 + j];
            const float4 b = *(const float4*)&bias[gcol + j];
            v.x = (v.x + b.x) * qs;
            v.y = (v.y + b.y) * qs;
            v.z = (v.z + b.z) * qs;
            v.w = (v.w + b.w) * qs;
            if (Ch) st_half4(&Ch[(size_t)grow * N + gcol + j], v);
            else    *(float4*)&Cf[(size_t)grow * N + gcol + j] = v;
        }
        __syncwarp();
    }
}

// ---------------------------------------------------------------------------
// Flash attention (fp16 S and PV), cp.async double-buffered K/V.
// (unchanged from the passing Round-15 kernel)
// ---------------------------------------------------------------------------
#define QLDH 72     // halfs (64 + 8)
#define KLDH 72
#define VLDH 88     // halfs (80 + 8); col 64 = ones
#define PLD  68     // floats (S / O staging)
#define PLDH 72     // halfs (P for mma)
#define KBUF_B (64 * KLDH * 2)     // 9216
#define VBUF_B (64 * VLDH * 2)     // 11264
#define AT_Q_B  0
#define AT_K0_B (AT_Q_B + 128 * QLDH * 2)          // 18432
#define AT_V0_B (AT_K0_B + 2 * KBUF_B)             // 36864
#define AT_P_B  (AT_V0_B + 2 * VBUF_B)             // 59392
#define AT_PH_B (AT_P_B + 128 * PLD * 4)           // 94208
#define ATTN_SMEM_BYTES (AT_PH_B + 128 * PLDH * 2) // 112640

__global__ __launch_bounds__(128) void attn_wmma_kernel()
{
    extern __shared__ char smraw[];
    __half* Qs = (__half*)(smraw + AT_Q_B);   // [128][QLDH]
    float*  Ps = (float*)(smraw + AT_P_B);    // [128][PLD] float S / O
    __half* Ph = (__half*)(smraw + AT_PH_B);  // [128][PLDH] half P

    const int tid  = threadIdx.x;
    const int lane = tid & 31, warp = tid >> 5;
    const int qb = warp * 32;
    const int rowIdx = lane >> 1, half = lane & 1;

    const int qt = blockIdx.x;           // 0..15
    const int bh = blockIdx.y;           // 0..63
    const int bb = bh >> 4, h = bh & (NH - 1);
    const size_t rowbase = (size_t)bb * SEQ;
    const int qcol = h * HS, kcol = EMB + h * HS, vcol = 2 * EMB + h * HS;

#define ATTN_ISSUE_KV(buf, kt)                                              \
    do {                                                                    \
        __half* Kd = (__half*)(smraw + AT_K0_B + (buf) * KBUF_B);           \
        __half* Vd = (__half*)(smraw + AT_V0_B + (buf) * VBUF_B);           \
        const __half* base = qkv_h + (rowbase + (kt) * 64) * N3;            \
        for (int i = tid; i < 512; i += 128) {                              \
            const int row = i >> 3, d = (i & 7) * 8;                        \
            __pipeline_memcpy_async(&Kd[row * KLDH + d],                    \
                                    base + (size_t)row * N3 + kcol + d, 16);\
            __pipeline_memcpy_async(&Vd[row * VLDH + d],                    \
                                    base + (size_t)row * N3 + vcol + d, 16);\
        }                                                                   \
        __pipeline_commit();                                                \
    } while (0)

    // Q tile: pure copy (pre-scaled, pre-biased)
    for (int i = tid * 8; i < 128 * HS; i += 128 * 8) {
        const int rr = i >> 6, d = i & 63;
        *(uint4*)&Qs[rr * QLDH + d] = *(const uint4*)(
            qkv_h + (rowbase + qt * 128 + rr) * N3 + qcol + d);
    }
    // ones-column region in BOTH V buffers (cols 64..79; only 64 = 1)
    for (int i = tid; i < 64 * 16; i += 128) {
        const int rr = i >> 4, c = 64 + (i & 15);
        const __half v = (c == 64) ? __float2half(1.0f) : __float2half(0.0f);
        ((__half*)(smraw + AT_V0_B))[rr * VLDH + c] = v;
        ((__half*)(smraw + AT_V0_B + VBUF_B))[rr * VLDH + c] = v;
    }
    // prologue: fill tile 0 into buf 0
    ATTN_ISSUE_KV(0, 0);

    wmma::fragment<wmma::accumulator, 16, 16, 16, float> pv[2][5];
#pragma unroll
    for (int mt = 0; mt < 2; mt++)
#pragma unroll
        for (int nt = 0; nt < 5; nt++)
            wmma::fill_fragment(pv[mt][nt], 0.0f);
    float mW = -1e30f;

    for (int kt = 0; kt < SEQ / 64; kt++) {
        __pipeline_wait_prior(0);
        __syncthreads();
        if (kt + 1 < SEQ / 64)
            ATTN_ISSUE_KV((kt + 1) & 1, kt + 1);

        const __half* Ks = (__half*)(smraw + AT_K0_B + (kt & 1) * KBUF_B);
        const __half* Vs = (__half*)(smraw + AT_V0_B + (kt & 1) * VBUF_B);

        // ---- S = Q @ K^T ----
        wmma::fragment<wmma::accumulator, 16, 16, 16, float> sacc[2][4];
#pragma unroll
        for (int mt = 0; mt < 2; mt++)
#pragma unroll
            for (int nt = 0; nt < 4; nt++)
                wmma::fill_fragment(sacc[mt][nt], 0.0f);
#pragma unroll
        for (int d0 = 0; d0 < HS; d0 += 16) {
            wmma::fragment<wmma::matrix_a, 16, 16, 16, __half,
                           wmma::row_major> af[2];
            wmma::load_matrix_sync(af[0], &Qs[qb * QLDH + d0], QLDH);
            wmma::load_matrix_sync(af[1], &Qs[(qb + 16) * QLDH + d0], QLDH);
#pragma unroll
            for (int nt = 0; nt < 4; nt++) {
                wmma::fragment<wmma::matrix_b, 16, 16, 16, __half,
                               wmma::col_major> bf;
                wmma::load_matrix_sync(bf, &Ks[(nt * 16) * KLDH + d0], KLDH);
#pragma unroll
                for (int mt = 0; mt < 2; mt++)
                    wmma::mma_sync(sacc[mt][nt], af[mt], bf, sacc[mt][nt]);
            }
        }

        // ---- warp-uniform online max ----
        float mx = -1e30f;
#pragma unroll
        for (int mt = 0; mt < 2; mt++)
#pragma unroll
            for (int nt = 0; nt < 4; nt++)
#pragma unroll
                for (int e = 0; e < sacc[mt][nt].num_elements; e++)
                    mx = fmaxf(mx, sacc[mt][nt].x[e]);
#pragma unroll
        for (int off = 16; off > 0; off >>= 1)
            mx = fmaxf(mx, __shfl_xor_sync(0xffffffff, mx, off));
        const float mn = fmaxf(mW, mx);
        const float corr = __expf(mW - mn);
        mW = mn;

        // ---- O *= corr ----
#pragma unroll
        for (int mt = 0; mt < 2; mt++)
#pragma unroll
            for (int nt = 0; nt < 5; nt++)
#pragma unroll
                for (int e = 0; e < pv[mt][nt].num_elements; e++)
                    pv[mt][nt].x[e] *= corr;

        // ---- P = exp(S - m) -> float tile -> half tile ----
#pragma unroll
        for (int mt = 0; mt < 2; mt++)
#pragma unroll
            for (int nt = 0; nt < 4; nt++) {
#pragma unroll
                for (int e = 0; e < sacc[mt][nt].num_elements; e++)
                    sacc[mt][nt].x[e] = __expf(sacc[mt][nt].x[e] - mn);
                wmma::store_matrix_sync(&Ps[(qb + mt * 16) * PLD + nt * 16],
                                        sacc[mt][nt], PLD,
                                        wmma::mem_row_major);
            }
        __syncwarp();
        for (int i = lane * 4; i < 32 * 64; i += 32 * 4) {
            const int rr = qb + (i >> 6), c = i & 63;
            st_half4(&Ph[rr * PLDH + c], *(const float4*)&Ps[rr * PLD + c]);
        }
        __syncwarp();

        // ---- O += P @ V' (ones col -> pv[mt][4] col0 = l) ----
#pragma unroll
        for (int kk = 0; kk < 64; kk += 16) {
            wmma::fragment<wmma::matrix_a, 16, 16, 16, __half,
                           wmma::row_major> af[2];
            wmma::load_matrix_sync(af[0], &Ph[qb * PLDH + kk], PLDH);
            wmma::load_matrix_sync(af[1], &Ph[(qb + 16) * PLDH + kk], PLDH);
#pragma unroll
            for (int nt = 0; nt < 5; nt++) {
                wmma::fragment<wmma::matrix_b, 16, 16, 16, __half,
                               wmma::row_major> bf;
                wmma::load_matrix_sync(bf, &Vs[kk * VLDH + nt * 16], VLDH);
#pragma unroll
                for (int mt = 0; mt < 2; mt++)
                    wmma::mma_sync(pv[mt][nt], af[mt], bf, pv[mt][nt]);
            }
        }
    }
#undef ATTN_ISSUE_KV

    // ---- epilogue: extract l, normalize, write half ----
    wmma::store_matrix_sync(&Ps[qb * PLD], pv[0][4], PLD,
                            wmma::mem_row_major);
    wmma::store_matrix_sync(&Ps[(qb + 16) * PLD], pv[1][4], PLD,
                            wmma::mem_row_major);
    __syncwarp();
    const float l0 = Ps[(qb + rowIdx) * PLD + 0];
    const float l1 = Ps[(qb + 16 + rowIdx) * PLD + 0];
    __syncwarp();
#pragma unroll
    for (int mt = 0; mt < 2; mt++)
#pragma unroll
        for (int nt = 0; nt < 4; nt++)
            wmma::store_matrix_sync(&Ps[(qb + mt * 16) * PLD + nt * 16],
                                    pv[mt][nt], PLD, wmma::mem_row_major);
    __syncwarp();

#pragma unroll
    for (int mt = 0; mt < 2; mt++) {
        const float inv = 1.0f / (mt ? l1 : l0);
        const int r = qb + mt * 16 + rowIdx;
        __half* orow = g_att_h + (size_t)(rowbase + qt * 128 + r) * EMB
                       + h * HS + half * 32;
        const float* prow = &Ps[r * PLD + half * 32];
#pragma unroll
        for (int j = 0; j < 32; j += 4) {
            const float4 o4 = *(const float4*)&prow[j];
            st_half4(&orow[j], make_float4(o4.x * inv, o4.y * inv,
                                           o4.z * inv, o4.w * inv));
        }
    }
}

// ---------------------------------------------------------------------------
extern "C" void kernel_launch(void* const* d_in, const int* in_sizes, int n_in,
                              void* d_out, int out_size)
{
    const float* x     = (const float*)d_in[0];
    const float* w_qkv = (const float*)d_in[1];
    const float* b_qkv = (const float*)d_in[2];
    const float* w_out = (const float*)d_in[3];
    const float* b_out = (const float*)d_in[4];
    float* out = (float*)d_out;

    __half *xh_p, *wq_p, *wo_p, *qkv_p, *att_p;
    cudaGetSymbolAddress((void**)&xh_p,  x_h);
    cudaGetSymbolAddress((void**)&wq_p,  wqkv_h);
    cudaGetSymbolAddress((void**)&wo_p,  wout_h);
    cudaGetSymbolAddress((void**)&qkv_p, qkv_h);
    cudaGetSymbolAddress((void**)&att_p, g_att_h);

    // convert inputs to half
    f2h_kernel<<<(MROWS * EMB) / 2048, 256>>>(x, xh_p);
    f2h_kernel<<<(EMB * N3) / 2048, 256>>>(w_qkv, wq_p);
    f2h_kernel<<<(EMB * EMB) / 2048, 256>>>(w_out, wo_p);

    // QKV projection: bias fused, q-cols pre-scaled by 1/8, half out
    gemm_h_kernel<<<dim3(N3 / 256, MROWS / 128), 256, GEMM_SMEM_BYTES>>>(
        xh_p, wq_p, b_qkv, qkv_p, nullptr, N3, 1);

    cudaFuncSetAttribute(attn_wmma_kernel,
                         cudaFuncAttributeMaxDynamicSharedMemorySize,
                         ATTN_SMEM_BYTES);
    attn_wmma_kernel<<<dim3(SEQ / 128, BATCH * NH), 128, ATTN_SMEM_BYTES>>>();

    // Output projection: bias fused, float out
    gemm_h_kernel<<<dim3(EMB / 256, MROWS / 128), 256, GEMM_SMEM_BYTES>>>(
        att_p, wo_p, b_out, nullptr, out, EMB, 0);
}